// round 5
// baseline (speedup 1.0000x reference)
#include <cuda_runtime.h>
#include <cuda_bf16.h>
#include <cuda_fp16.h>
#include <cstdint>

// ---------------- problem constants ----------------
#define TSZ   512
#define NTILE 64
#define ITN   8

#define GMIN   1e-6f
#define GDIFF  ((float)(1.0e-4 - 1.0e-6))
#define STEPQ  ((float)((1.0e-4 - 1.0e-6) / 15.0))
#define FINF   3.402823466e38f
#define GSCALE 8192.0f
#define GINV   (1.0f / 8192.0f)

typedef unsigned int uint32;
typedef unsigned long long ull;

// ---------------- scratch (static device memory) ----------------
__device__ __half g_x16[(size_t)1024 * 4096];
__device__ __half g_Gh[(size_t)NTILE * TSZ * TSZ];   // geff*8192 hi, [t][n][k]
__device__ __half g_Gl[(size_t)NTILE * TSZ * TSZ];   // geff*8192 lo
__device__ __half g_Qi[(size_t)NTILE * TSZ * TSZ];   // quant code 0..15
__device__ float g_cur [(size_t)NTILE * 1024 * TSZ];  // 128 MB
__device__ float g_part[(size_t)NTILE * 4 * 1024 * 6];
__device__ float g_s[NTILE], g_wmin[NTILE];
__device__ float g_pmin[NTILE * 8], g_pmax[NTILE * 8];
__device__ float g_xsum[1024 * ITN];

// ---------------- PTX helpers ----------------
__device__ __forceinline__ uint32 smem_u32(const void* p) {
    uint32 a;
    asm("{ .reg .u64 t; cvta.to.shared.u64 t, %1; cvt.u32.u64 %0, t; }" : "=r"(a) : "l"(p));
    return a;
}
__device__ __forceinline__ void cpa16(uint32 dst, const void* src) {
    asm volatile("cp.async.cg.shared.global [%0], [%1], 16;" :: "r"(dst), "l"(src));
}
__device__ __forceinline__ void ldm_x4(uint32* r, uint32 addr) {
    asm volatile("ldmatrix.sync.aligned.m8n8.x4.shared.b16 {%0,%1,%2,%3}, [%4];"
                 : "=r"(r[0]), "=r"(r[1]), "=r"(r[2]), "=r"(r[3]) : "r"(addr));
}
__device__ __forceinline__ void mma16816(float* c, const uint32* a, const uint32* b) {
    asm volatile(
        "mma.sync.aligned.m16n8k16.row.col.f32.f16.f16.f32 "
        "{%0,%1,%2,%3}, {%4,%5,%6,%7}, {%8,%9}, {%0,%1,%2,%3};"
        : "+f"(c[0]), "+f"(c[1]), "+f"(c[2]), "+f"(c[3])
        : "r"(a[0]), "r"(a[1]), "r"(a[2]), "r"(a[3]), "r"(b[0]), "r"(b[1]));
}

// ---------------- kernel 1a: per-tile min/max partials ----------------
__global__ void k_minmax_part(const float* __restrict__ w) {
    int t = blockIdx.y, chunk = blockIdx.x;
    int it = t >> 3, ot = t & 7;
    int tid = threadIdx.x;
    float mn = FINF, mx = -FINF;
    int base = chunk * 32768 + tid;
    #pragma unroll 4
    for (int k = 0; k < 128; k++) {
        int e = base + k * 256;
        int i = e >> 9, j = e & 511;
        float v = w[(size_t)(it * TSZ + i) * 4096 + ot * TSZ + j];
        mn = fminf(mn, v); mx = fmaxf(mx, v);
    }
    __shared__ float smn[256], smx[256];
    smn[tid] = mn; smx[tid] = mx;
    __syncthreads();
    for (int o = 128; o > 0; o >>= 1) {
        if (tid < o) {
            smn[tid] = fminf(smn[tid], smn[tid + o]);
            smx[tid] = fmaxf(smx[tid], smx[tid + o]);
        }
        __syncthreads();
    }
    if (tid == 0) { g_pmin[t * 8 + chunk] = smn[0]; g_pmax[t * 8 + chunk] = smx[0]; }
}

__global__ void k_minmax_fin() {
    int t = threadIdx.x;
    if (t < NTILE) {
        float mn = g_pmin[t * 8], mx = g_pmax[t * 8];
        #pragma unroll
        for (int c = 1; c < 8; c++) {
            mn = fminf(mn, g_pmin[t * 8 + c]);
            mx = fmaxf(mx, g_pmax[t * 8 + c]);
        }
        float denom = __fadd_rn(__fsub_rn(mx, mn), 1e-12f);
        g_s[t] = __fdiv_rn(GDIFF, denom);
        g_wmin[t] = mn;
    }
}

// ---------------- kernel 2: build Gh/Gl/Qi (fp16, scaled), TRANSPOSED [t][n][k] ----------------
__global__ void __launch_bounds__(256) k_build(const float* __restrict__ w) {
    __shared__ __half sGh[64][72], sGl[64][72], sQi[64][72];
    int sub = blockIdx.x, t = blockIdx.y;
    int it = t >> 3, ot = t & 7;
    int ib = sub >> 3, jb = sub & 7;
    int i0 = ib * 64, j0 = jb * 64;
    int tid = threadIdx.x;
    float s = g_s[t], wmin = g_wmin[t];

    #pragma unroll
    for (int iter = 0; iter < 16; iter++) {
        int e = iter * 256 + tid;
        int i = e >> 6, j = e & 63;       // i: k, j: n
        float v = w[(size_t)(it * TSZ + i0 + i) * 4096 + ot * TSZ + j0 + j];
        // bit-exact reference op sequence:
        float t1   = __fsub_rn(v, wmin);
        float t2   = __fmul_rn(t1, s);
        float cond = __fadd_rn(t2, GMIN);
        float u    = __fsub_rn(cond, GMIN);
        float vv   = __fdiv_rn(u, STEPQ);
        float q    = rintf(vv);                       // 0..15, exact in fp16
        float cq   = __fadd_rn(__fmul_rn(q, STEPQ), GMIN);
        float inv  = __fdiv_rn(1.0f, cq);
        float rw   = (float)(2 * (513 + (j0 + j) - (i0 + i)));
        float ge   = __fdiv_rn(1.0f, __fadd_rn(inv, rw));
        float gs   = ge * GSCALE;                     // exact pow2 scale
        __half gh  = __float2half_rn(gs);
        __half gl  = __float2half_rn(__fsub_rn(gs, __half2float(gh)));
        sGh[j][i] = gh; sGl[j][i] = gl; sQi[j][i] = __float2half_rn(q);
    }
    __syncthreads();

    size_t obase = (size_t)t * 262144 + (size_t)j0 * 512 + i0;
    #pragma unroll
    for (int iter = 0; iter < 2; iter++) {
        int L = iter * 256 + tid;
        int n = L >> 3, k8 = (L & 7) * 8;
        size_t o = obase + (size_t)n * 512 + k8;
        *(uint4*)&g_Gh[o] = *(const uint4*)&sGh[n][k8];
        *(uint4*)&g_Gl[o] = *(const uint4*)&sGl[n][k8];
        *(uint4*)&g_Qi[o] = *(const uint4*)&sQi[n][k8];
    }
}

// ---------------- kernel 2b: x -> fp16 + per-(b,it) row sums, fused ----------------
// grid (8192) = (b*8+it), 128 threads x 4 elems
__global__ void k_xprep(const float* __restrict__ x) {
    int blk = blockIdx.x;
    int b = blk >> 3, it = blk & 7;
    int tid = threadIdx.x;
    size_t base = (size_t)b * 4096 + it * TSZ + tid * 4;
    float4 v = *(const float4*)&x[base];
    __half h[4] = { __float2half_rn(v.x), __float2half_rn(v.y),
                    __float2half_rn(v.z), __float2half_rn(v.w) };
    *(ull*)&g_x16[base] = *(const ull*)h;
    float s = v.x + v.y + v.z + v.w;
    #pragma unroll
    for (int o = 16; o > 0; o >>= 1) s += __shfl_down_sync(0xffffffffu, s, o);
    __shared__ float sm[4];
    if ((tid & 31) == 0) sm[tid >> 5] = s;
    __syncthreads();
    if (tid == 0) g_xsum[b * ITN + it] = sm[0] + sm[1] + sm[2] + sm[3];
}

// ---------------- kernel 4: mma.sync dual GEMM (3 passes, fp16) ----------------
// grid (nb=4, mb=8, t=64), 256 threads. CTA tile 128x128, K=512, k-chunk 32.
#define PITCH 80
#define OFF_X  0
#define OFF_GH 10240
#define OFF_GL 20480
#define OFF_QI 30720
#define STAGE 40960
#define SMEM_GEMM (2 * STAGE)

__global__ void __launch_bounds__(256, 1) k_gemm() {
    extern __shared__ char smem[];
    uint32 sb = smem_u32(smem);
    int tid = threadIdx.x;
    int nb = blockIdx.x, mb = blockIdx.y, t = blockIdx.z;
    int it = t >> 3;

    const __half* Ax = g_x16 + (size_t)(mb * 128) * 4096 + it * 512;
    size_t bbase = (size_t)t * 262144 + (size_t)(nb * 128) * 512;
    const __half* Bh = g_Gh + bbase;
    const __half* Bl = g_Gl + bbase;
    const __half* Bq = g_Qi + bbase;

    float acc_c[4][4][4];
    float acc_i[4][4][4];
    #pragma unroll
    for (int i = 0; i < 4; i++)
        #pragma unroll
        for (int j = 0; j < 4; j++)
            #pragma unroll
            for (int r = 0; r < 4; r++) { acc_c[i][j][r] = 0.f; acc_i[i][j][r] = 0.f; }

    auto issue = [&](int c) {
        uint32 sbuf = sb + (c & 1) * STAGE;
        int kk = c * 32;
        #pragma unroll
        for (int L0 = 0; L0 < 2; L0++) {
            int L = L0 * 256 + tid;
            int r = L >> 2, ch = L & 3;
            uint32 d = sbuf + r * PITCH + ch * 16;
            int soA = r * 4096 + kk + ch * 8;
            int soB = r * 512  + kk + ch * 8;
            cpa16(d + OFF_X,  Ax + soA);
            cpa16(d + OFF_GH, Bh + soB);
            cpa16(d + OFF_GL, Bl + soB);
            cpa16(d + OFF_QI, Bq + soB);
        }
        asm volatile("cp.async.commit_group;");
    };

    int lane = tid & 31, wid = tid >> 5;
    int wm0 = (wid >> 2) * 64, wn0 = (wid & 3) * 32;
    int wnid = wid & 3;
    int a_row = lane & 15;
    int a_koff = ((lane >> 4) & 1) * 16;
    int b_row = ((lane >> 4) & 1) * 8 + (lane & 7);
    int b_koff = ((lane >> 3) & 1) * 16;

    issue(0);
    for (int c = 0; c < 16; c++) {
        if (c < 15) {
            issue(c + 1);
            asm volatile("cp.async.wait_group 1;" ::: "memory");
        } else {
            asm volatile("cp.async.wait_group 0;" ::: "memory");
        }
        __syncthreads();
        uint32 sbuf = sb + (c & 1) * STAGE;

        #pragma unroll
        for (int ks = 0; ks < 2; ks++) {
            uint32 kb = ks * 32;
            uint32 ax[4][4];
            #pragma unroll
            for (int i = 0; i < 4; i++) {
                uint32 ad = sbuf + (uint32)(wm0 + i * 16 + a_row) * PITCH + kb + a_koff;
                ldm_x4(ax[i], ad + OFF_X);
            }
            uint32 gh[4][2], gl[4][2], qi[4][2];
            #pragma unroll
            for (int j2 = 0; j2 < 2; j2++) {
                uint32 bd = sbuf + (uint32)(wn0 + j2 * 16 + b_row) * PITCH + kb + b_koff;
                uint32 r4[4];
                ldm_x4(r4, bd + OFF_GH);
                gh[2*j2][0] = r4[0]; gh[2*j2][1] = r4[1];
                gh[2*j2+1][0] = r4[2]; gh[2*j2+1][1] = r4[3];
                ldm_x4(r4, bd + OFF_GL);
                gl[2*j2][0] = r4[0]; gl[2*j2][1] = r4[1];
                gl[2*j2+1][0] = r4[2]; gl[2*j2+1][1] = r4[3];
                ldm_x4(r4, bd + OFF_QI);
                qi[2*j2][0] = r4[0]; qi[2*j2][1] = r4[1];
                qi[2*j2+1][0] = r4[2]; qi[2*j2+1][1] = r4[3];
            }
            #pragma unroll
            for (int i = 0; i < 4; i++)
                #pragma unroll
                for (int j = 0; j < 4; j++) {
                    mma16816(acc_c[i][j], ax[i], gh[j]);
                    mma16816(acc_c[i][j], ax[i], gl[j]);
                    mma16816(acc_i[i][j], ax[i], qi[j]);
                }
        }
        __syncthreads();
    }

    // ---- epilogue: rescale currents, store, per-row stats of both accs ----
    int grp = lane >> 2, qd = lane & 3;
    size_t rowbase = (size_t)t * 1024 + (size_t)mb * 128;
    #pragma unroll
    for (int i = 0; i < 4; i++)
        #pragma unroll
        for (int j = 0; j < 4; j++)
            #pragma unroll
            for (int r = 0; r < 4; r++) acc_c[i][j][r] *= GINV;

    #pragma unroll
    for (int i = 0; i < 4; i++)
        #pragma unroll
        for (int h = 0; h < 2; h++) {
            int r = wm0 + i * 16 + h * 8 + grp;
            size_t gbb = (rowbase + r) * 512 + nb * 128 + wn0 + qd * 2;
            #pragma unroll
            for (int j = 0; j < 4; j++)
                *(float2*)&g_cur[gbb + j * 8] =
                    make_float2(acc_c[i][j][2*h], acc_c[i][j][2*h+1]);
        }

    float* stats = (float*)smem;   // [128 rows][4 nwarps][6]
    #pragma unroll
    for (int i = 0; i < 4; i++)
        #pragma unroll
        for (int h = 0; h < 2; h++) {
            float cs = 0.f, cmx = -FINF, cmn = FINF;
            float is_ = 0.f, imx = -FINF, imn = FINF;
            #pragma unroll
            for (int j = 0; j < 4; j++) {
                float v0 = acc_c[i][j][2*h], v1 = acc_c[i][j][2*h+1];
                cs += v0 + v1; cmx = fmaxf(cmx, fmaxf(v0, v1)); cmn = fminf(cmn, fminf(v0, v1));
                float u0 = acc_i[i][j][2*h], u1 = acc_i[i][j][2*h+1];
                is_ += u0 + u1; imx = fmaxf(imx, fmaxf(u0, u1)); imn = fminf(imn, fminf(u0, u1));
            }
            #pragma unroll
            for (int o = 1; o <= 2; o <<= 1) {
                cs  += __shfl_xor_sync(0xffffffffu, cs, o);
                cmx  = fmaxf(cmx, __shfl_xor_sync(0xffffffffu, cmx, o));
                cmn  = fminf(cmn, __shfl_xor_sync(0xffffffffu, cmn, o));
                is_ += __shfl_xor_sync(0xffffffffu, is_, o);
                imx  = fmaxf(imx, __shfl_xor_sync(0xffffffffu, imx, o));
                imn  = fminf(imn, __shfl_xor_sync(0xffffffffu, imn, o));
            }
            if (qd == 0) {
                int r = wm0 + i * 16 + h * 8 + grp;
                float* p = &stats[(r * 4 + wnid) * 6];
                p[0] = cs; p[1] = cmx; p[2] = cmn; p[3] = is_; p[4] = imx; p[5] = imn;
            }
        }
    __syncthreads();
    if (tid < 128) {
        float cs = 0.f, cmx = -FINF, cmn = FINF;
        float is_ = 0.f, imx = -FINF, imn = FINF;
        #pragma unroll
        for (int wn = 0; wn < 4; wn++) {
            const float* p = &stats[(tid * 4 + wn) * 6];
            cs += p[0]; cmx = fmaxf(cmx, p[1]); cmn = fminf(cmn, p[2]);
            is_ += p[3]; imx = fmaxf(imx, p[4]); imn = fminf(imn, p[5]);
        }
        float* p = &g_part[(((size_t)t * 4 + nb) * 1024 + (mb * 128 + tid)) * 6];
        p[0] = cs; p[1] = cmx; p[2] = cmn; p[3] = is_; p[4] = imx; p[5] = imn;
    }
}

// ---------------- kernel 5: combine ----------------
__global__ void __launch_bounds__(512) k_combine(const float* __restrict__ bias,
                                                 float* __restrict__ out) {
    int ot = blockIdx.x, b = blockIdx.y, j = threadIdx.x;
    float acc = 0.0f;
    #pragma unroll
    for (int it = 0; it < ITN; it++) {
        int t = it * 8 + ot;
        float cs = 0.f, cmx = -FINF, cmn = FINF, as_ = 0.f, amx = -FINF, amn = FINF;
        #pragma unroll
        for (int nb = 0; nb < 4; nb++) {
            const float* p = &g_part[(((size_t)t * 4 + nb) * 1024 + b) * 6];
            cs += p[0]; cmx = fmaxf(cmx, p[1]); cmn = fminf(cmn, p[2]);
            as_ += p[3]; amx = fmaxf(amx, p[4]); amn = fminf(amn, p[5]);
        }
        float cur = g_cur[((size_t)t * 1024 + b) * 512 + j];
        float xs = g_xsum[b * ITN + it];
        // ideal = STEPQ * a + GMIN * xs (monotone transform of raw accumulator a)
        float cmean = cs * (1.0f / 512.0f);
        float imean = __fmul_rn(STEPQ, as_ * (1.0f / 512.0f)) + __fmul_rn(GMIN, xs);
        float coeff = __fdiv_rn(__fmul_rn(STEPQ, __fsub_rn(amx, amn)),
                                __fadd_rn(__fsub_rn(cmx, cmn), 1e-8f));
        float s = g_s[t], wmin = g_wmin[t];
        float off = __fmul_rn(xs, __fsub_rn(GMIN, __fmul_rn(s, wmin)));
        float val = __fadd_rn(__fmul_rn(__fsub_rn(cur, cmean), coeff), imean);
        acc += __fdiv_rn(__fsub_rn(val, off), s);
    }
    out[(size_t)b * 4096 + ot * TSZ + j] = __fadd_rn(acc, bias[ot * TSZ + j]);
}

// ---------------- launch ----------------
extern "C" void kernel_launch(void* const* d_in, const int* in_sizes, int n_in,
                              void* d_out, int out_size) {
    const float* x = nullptr; const float* w = nullptr; const float* bias = nullptr;
    for (int i = 0; i < n_in; i++) {
        if (in_sizes[i] == 1024 * 4096)      x    = (const float*)d_in[i];
        else if (in_sizes[i] == 4096 * 4096) w    = (const float*)d_in[i];
        else if (in_sizes[i] == 4096)        bias = (const float*)d_in[i];
    }
    float* out = (float*)d_out;

    cudaFuncSetAttribute(k_gemm, cudaFuncAttributeMaxDynamicSharedMemorySize, SMEM_GEMM);

    k_minmax_part<<<dim3(8, 64), 256>>>(w);
    k_minmax_fin<<<1, 64>>>();
    k_build<<<dim3(64, 64), 256>>>(w);
    k_xprep<<<8192, 128>>>(x);
    k_gemm<<<dim3(4, 8, 64), 256, SMEM_GEMM>>>();
    k_combine<<<dim3(8, 1024), 512>>>(bias, out);
}